// round 16
// baseline (speedup 1.0000x reference)
#include <cuda_runtime.h>

#define FDIM 1024
#define CDIM 64
#define NROWS 65536
#define TR 32
#define NTILES (NROWS / TR)          // 2048
#define NTHREADS 512
#define NWARPS 16
#define NBLOCKS 148
#define VSTR 33                      // value row stride (floats)
#define PADLIST 1280                 // padded concatenated member lists

// dynamic smem float offsets
#define OFF_SV    0
#define OFF_SMAX  (1025 * VSTR)                 // 64*33
#define OFF_SSUM  (OFF_SMAX + CDIM * VSTR)
#define OFF_PTOT  (OFF_SSUM + CDIM * VSTR)      // 16*33
#define OFF_PSM   (OFF_PTOT + NWARPS * VSTR)
#define OFF_END_F (OFF_PSM + NWARPS * VSTR)
#define OFF_ORD_B   (((OFF_END_F * 4) + 7) & ~7)          // 8-aligned ushorts
#define OFF_GBASE_B (OFF_ORD_B + PADLIST * 2)
#define OFF_LAB_B   (OFF_GBASE_B + (CDIM + 1) * 4)
#define SMEM_BYTES  (OFF_LAB_B + TR * 4)

// Scratch (no allocations allowed)
__device__ __align__(8) unsigned short g_ord[PADLIST]; // member lists (sentinel 1024)
__device__ int    g_gbase[CDIM + 1];                   // padded list starts
__device__ double g_acc[64];

// ---------------------------------------------------------------------------
// Setup <<<1,1024>>>: seg via one-hot dot product, padded member lists.
// ---------------------------------------------------------------------------
__global__ void setup_kernel(const float* __restrict__ mask) {
    __shared__ int scnt[CDIM];
    __shared__ int sbase[CDIM];
    __shared__ int s_w0sum;
    const int f = threadIdx.x, lane = f & 31;

    if (f < CDIM) scnt[f] = 0;
    for (int i = f; i < PADLIST; i += 1024)
        g_ord[i] = (unsigned short)1024;          // sentinel (reads 0.0)
    __syncthreads();

    const float4* mrow = (const float4*)(mask + f * CDIM);
    float acc = 0.f;
#pragma unroll
    for (int q = 0; q < 16; q++) {
        float4 m = mrow[q];
        float c0 = (float)(4 * q);
        acc = fmaf(m.x, c0, acc);       acc = fmaf(m.y, c0 + 1.f, acc);
        acc = fmaf(m.z, c0 + 2.f, acc); acc = fmaf(m.w, c0 + 3.f, acc);
    }
    const int s = (int)(acc + 0.5f);
    const int r = atomicAdd(&scnt[s], 1);
    __syncthreads();

    int v = 0, sc = 0;
    if (f < CDIM) {
        v = (scnt[f] + 3) & ~3;                   // pad to ushort4 steps
        sc = v;
#pragma unroll
        for (int o = 1; o < 32; o <<= 1) {
            int n = __shfl_up_sync(~0u, sc, o);
            if (lane >= o) sc += n;
        }
        if (f == 31) s_w0sum = sc;
    }
    __syncthreads();
    if (f < CDIM) {
        int base = sc - v + ((f >= 32) ? s_w0sum : 0);
        sbase[f] = base;
        g_gbase[f] = base;
        if (f == 63) g_gbase[64] = base + v;
        g_acc[f] = 0.0;                           // re-zero every replay
    }
    __syncthreads();

    g_ord[sbase[s] + r] = (unsigned short)f;
}

// ---------------------------------------------------------------------------
// Main: 1 block/SM, 512 thr, 32-row transposed tile sv[f][r] (stride 33 =
// conflict-free stores AND loads). Phase1: exp+store at natural f (2 rows
// per warp) + prefetch next tile. Phase2: per-group (max,sum) with lane=row.
// ---------------------------------------------------------------------------
__global__ void __launch_bounds__(NTHREADS, 1) mix_kernel(
    const float* __restrict__ logits,
    const int*   __restrict__ labels)
{
    extern __shared__ float sm[];
    float* sv   = sm + OFF_SV;
    float* smax = sm + OFF_SMAX;
    float* ssum = sm + OFF_SSUM;
    float* ptot = sm + OFF_PTOT;
    float* psm  = sm + OFF_PSM;
    unsigned short* sord = (unsigned short*)((char*)sm + OFF_ORD_B);
    int* sgbase = (int*)((char*)sm + OFF_GBASE_B);
    int* slab   = (int*)((char*)sm + OFF_LAB_B);

    const int t = threadIdx.x, lane = t & 31, w = t >> 5;

    if (t < PADLIST / 4)
        ((ushort4*)sord)[t] = ((const ushort4*)g_ord)[t];
    if (t >= NTHREADS - (CDIM + 1))               // different warps than copy
        sgbase[t - (NTHREADS - (CDIM + 1))] = g_gbase[t - (NTHREADS - (CDIM + 1))];
    if (t < VSTR) sv[1024 * VSTR + t] = 0.f;      // sentinel row = 0
    __syncthreads();

    const int r0 = 2 * w, r1 = 2 * w + 1;
    int tile = blockIdx.x;

    float4 va[8], vb[8];
    {
        const float4* pa = (const float4*)(logits + ((size_t)tile * TR + r0) * FDIM);
        const float4* pb = (const float4*)(logits + ((size_t)tile * TR + r1) * FDIM);
#pragma unroll
        for (int c = 0; c < 8; c++) va[c] = pa[lane + 32 * c];
#pragma unroll
        for (int c = 0; c < 8; c++) vb[c] = pb[lane + 32 * c];
    }

    for (; tile < NTILES; tile += NBLOCKS) {
        // ---- phase 1: exp + conflict-free natural-index store ----
        {
            const int base0 = (4 * lane) * VSTR + r0;
#pragma unroll
            for (int c = 0; c < 8; c++) {
                int ba = base0 + c * 128 * VSTR;
                sv[ba           ] = __expf(va[c].x);
                sv[ba +     VSTR] = __expf(va[c].y);
                sv[ba + 2 * VSTR] = __expf(va[c].z);
                sv[ba + 3 * VSTR] = __expf(va[c].w);
                int bb = ba + 1;                     // r1 = r0 + 1
                sv[bb           ] = __expf(vb[c].x);
                sv[bb +     VSTR] = __expf(vb[c].y);
                sv[bb + 2 * VSTR] = __expf(vb[c].z);
                sv[bb + 3 * VSTR] = __expf(vb[c].w);
            }
        }
        if (t < TR) slab[t] = labels[tile * TR + t];

        // prefetch next tile (lands during scan)
        {
            int nt = tile + NBLOCKS;
            if (nt < NTILES) {
                const float4* pa = (const float4*)(logits + ((size_t)nt * TR + r0) * FDIM);
                const float4* pb = (const float4*)(logits + ((size_t)nt * TR + r1) * FDIM);
#pragma unroll
                for (int c = 0; c < 8; c++) va[c] = pa[lane + 32 * c];
#pragma unroll
                for (int c = 0; c < 8; c++) vb[c] = pb[lane + 32 * c];
            }
        }
        __syncthreads();

        // ---- phase 2: per-group (max,sum), lane = row ----
        {
            const float* svr = sv + lane;
#pragma unroll
            for (int gi = 0; gi < 4; gi++) {
                const int g = 4 * w + gi;
                const int kb = sgbase[g], ke = sgbase[g + 1];
                float gmx = 0.f, gsm = 0.f;
                for (int k = kb; k < ke; k += 4) {
                    ushort4 m = *(const ushort4*)(sord + k);
                    float x0 = svr[(int)m.x * VSTR];
                    float x1 = svr[(int)m.y * VSTR];
                    float x2 = svr[(int)m.z * VSTR];
                    float x3 = svr[(int)m.w * VSTR];
                    gsm += (x0 + x1) + (x2 + x3);
                    gmx = fmaxf(gmx, fmaxf(fmaxf(x0, x1), fmaxf(x2, x3)));
                }
                smax[g * VSTR + lane] = gmx;   // = exp(coarse_max)
                ssum[g * VSTR + lane] = gsm;   // = group exp-sum
            }
        }
        __syncthreads();

        // ---- partials across this warp's 4 groups ----
        {
            float pt = 0.f, ps = 0.f;
#pragma unroll
            for (int gi = 0; gi < 4; gi++) {
                const int g = 4 * w + gi;
                pt += ssum[g * VSTR + lane];
                ps += smax[g * VSTR + lane];
            }
            ptot[w * VSTR + lane] = pt;
            psm [w * VSTR + lane] = ps;
        }
        __syncthreads();

        // ---- warp 0: per-row loss ----
        if (w == 0) {
            float tot = 0.f, S = 0.f;
#pragma unroll
            for (int q = 0; q < NWARPS; q++) {
                tot += ptot[q * VSTR + lane];
                S   += psm [q * VSTR + lane];
            }
            const int lab = slab[lane];
            const float ls  = ssum[lab * VSTR + lane];
            const float gml = smax[lab * VSTR + lane];
            float loss = 0.5f * ((logf(S) - logf(gml)) + (logf(tot) - logf(ls)));
#pragma unroll
            for (int o = 16; o; o >>= 1)
                loss += __shfl_xor_sync(~0u, loss, o);
            if (lane == 0) atomicAdd(&g_acc[tile & 63], (double)loss);
        }
    }
}

// ---------------------------------------------------------------------------
// Finalize: mean over rows -> d_out[0]
// ---------------------------------------------------------------------------
__global__ void finalize_kernel(float* __restrict__ out) {
    double s = 0.0;
#pragma unroll
    for (int i = 0; i < 64; i++) s += g_acc[i];
    out[0] = (float)(s / (double)NROWS);
}

extern "C" void kernel_launch(void* const* d_in, const int* in_sizes, int n_in,
                              void* d_out, int out_size) {
    const float* logits = (const float*)d_in[0];  // [32, 2048, 1024] f32
    const int*   labels = (const int*)d_in[1];    // [32, 2048] i32
    const float* mask   = (const float*)d_in[2];  // [1024, 64] f32

    cudaFuncSetAttribute(mix_kernel,
                         cudaFuncAttributeMaxDynamicSharedMemorySize, SMEM_BYTES);
    setup_kernel<<<1, 1024>>>(mask);
    mix_kernel<<<NBLOCKS, NTHREADS, SMEM_BYTES>>>(logits, labels);
    finalize_kernel<<<1, 1>>>((float*)d_out);
}

// round 17
// speedup vs baseline: 1.0404x; 1.0404x over previous
#include <cuda_runtime.h>

#define FDIM 1024
#define CDIM 64
#define NROWS 65536
#define RPB 8                          // warps (row streams) per block
#define NTHREADS (RPB * 32)
#define NBLOCKS (148 * 4)              // one resident wave: 4 blocks/SM
#define NWARPS_TOTAL (NBLOCKS * RPB)
#define PADF 1216                      // padded sorted positions (1024 + 64*3)

// Scratch (no allocations allowed; zero-initialized at module load)
__device__ unsigned short g_meta16[FDIM];     // bank-matched sorted position per f
__device__ int            g_pstart[CDIM + 1]; // padded group boundaries
__device__ double         g_acc[64];          // interleaved loss accumulators
__device__ int            g_done;             // finished-block counter
__device__ int            g_flag;             // setup-done flag

__global__ void __launch_bounds__(NTHREADS, 4) mix_kernel(
    const float* __restrict__ logits,
    const int*   __restrict__ labels,
    const float* __restrict__ mask,
    float*       __restrict__ out)
{
    __shared__ float          sslice[RPB][PADF];   // 38 KB exp-domain sorted rows
    __shared__ unsigned short smeta16[FDIM];       // 2 KB positions
    __shared__ int            spstart[CDIM + 1];
    // setup scratch (block 0 only)
    __shared__ int            scnt[CDIM];
    __shared__ int            sbase[CDIM];
    __shared__ int            s_w0sum;
    __shared__ unsigned short ord[PADF];

    const int t    = threadIdx.x;
    const int lane = t & 31;
    const int w    = t >> 5;

    // ================= Setup (block 0) / wait (others) =================
    if (blockIdx.x == 0) {
        if (t < CDIM) { scnt[t] = 0; g_acc[t] = 0.0; }
        __syncthreads();

        int segs[4], ranks[4];
#pragma unroll
        for (int i = 0; i < 4; i++) {
            int f = t + 256 * i;
            const float4* mrow = (const float4*)(mask + f * CDIM);
            float acc = 0.f;
#pragma unroll
            for (int q = 0; q < 16; q++) {
                float4 m = mrow[q];
                float c0 = (float)(4 * q);
                acc = fmaf(m.x, c0, acc);       acc = fmaf(m.y, c0 + 1.f, acc);
                acc = fmaf(m.z, c0 + 2.f, acc); acc = fmaf(m.w, c0 + 3.f, acc);
            }
            segs[i]  = (int)(acc + 0.5f);                 // one-hot argmax
            ranks[i] = atomicAdd(&scnt[segs[i]], 1);
        }
        __syncthreads();

        // exclusive prefix of 4-padded group counts
        int v = 0, sc = 0;
        if (t < CDIM) {
            v = (scnt[t] + 3) & ~3;
            sc = v;
#pragma unroll
            for (int o = 1; o < 32; o <<= 1) {
                int n = __shfl_up_sync(~0u, sc, o);
                if (lane >= o) sc += n;
            }
            if (t == 31) s_w0sum = sc;
        }
        __syncthreads();
        if (t < CDIM) {
            int base = sc - v + ((t >= 32) ? s_w0sum : 0);
            sbase[t] = base;
            g_pstart[t] = base;
            if (t == 63) g_pstart[64] = base + v;
        }
        __syncthreads();

        // member lists per group
#pragma unroll
        for (int i = 0; i < 4; i++)
            ord[sbase[segs[i]] + ranks[i]] = (unsigned short)(t + 256 * i);
        __syncthreads();

        // per-group bank matching (bounded loops only)
        if (t < CDIM) {
            const int base = sbase[t];
            const int len  = scnt[t];
            if (len >= 1 && len <= 32) {
                const unsigned lenmask =
                    (len == 32) ? 0xFFFFFFFFu : ((1u << len) - 1u);
                unsigned taken = 0;
                for (int j = 0; j < len; j++) {          // pass 1: bank == lane
                    int f = ord[base + j];
                    int ln = (f >> 2) & 31;
                    int i = (ln - base) & 31;
                    if (i < len && !((taken >> i) & 1u)) {
                        g_meta16[f] = (unsigned short)(base + i);
                        taken |= 1u << i;
                        ord[base + j] = 0xFFFF;
                    }
                }
                for (int j = 0; j < len; j++) {          // pass 2: ffs free slot
                    int f = ord[base + j];
                    if (f == 0xFFFF) continue;
                    unsigned freebits = (~taken) & lenmask;
                    int i = freebits ? (__ffs(freebits) - 1) : j;
                    g_meta16[f] = (unsigned short)(base + i);
                    taken |= 1u << i;
                }
            } else {
                for (int j = 0; j < len; j++)
                    g_meta16[ord[base + j]] = (unsigned short)(base + j);
            }
        }
        __threadfence();
        __syncthreads();
        if (t == 0) *(volatile int*)&g_flag = 1;
    } else {
        if (t == 0) { while (*(volatile int*)&g_flag == 0) {} }
        __syncthreads();
    }

    // ================= Block prologue =================
    reinterpret_cast<uint2*>(smeta16)[t] = reinterpret_cast<const uint2*>(g_meta16)[t];
    if (t <= CDIM) spstart[t] = g_pstart[t];
    __syncthreads();

    float*  my  = sslice[w];
    float4* my4 = reinterpret_cast<float4*>(my);
    for (int i = lane; i < PADF / 4; i += 32)      // pads stay 0 (exp domain)
        my4[i] = make_float4(0.f, 0.f, 0.f, 0.f);
    __syncwarp();

    const int a0 = spstart[lane],      b0 = spstart[lane + 1];
    const int a1 = spstart[lane + 32], b1 = spstart[lane + 33];
    const ushort4* mp = reinterpret_cast<const ushort4*>(smeta16);

    // ================= Row loop =================
    for (int row = blockIdx.x * RPB + w; row < NROWS; row += NWARPS_TOTAL) {
        const float4* rp = reinterpret_cast<const float4*>(logits + (size_t)row * FDIM);
        float4 v0 = rp[lane];
        float4 v1 = rp[lane + 32];
        float4 v2 = rp[lane + 64];
        float4 v3 = rp[lane + 96];
        float4 v4 = rp[lane + 128];
        float4 v5 = rp[lane + 160];
        float4 v6 = rp[lane + 192];
        float4 v7 = rp[lane + 224];

        // exp + bank-matched scatter (no per-element label work)
#define DO_CHUNK(VV, CI)                                                     \
        {                                                                    \
            ushort4 m = mp[lane + 32 * (CI)];                                \
            my[m.x] = __expf(VV.x);                                          \
            my[m.y] = __expf(VV.y);                                          \
            my[m.z] = __expf(VV.z);                                          \
            my[m.w] = __expf(VV.w);                                          \
        }
        DO_CHUNK(v0, 0) DO_CHUNK(v1, 1) DO_CHUNK(v2, 2) DO_CHUNK(v3, 3)
        DO_CHUNK(v4, 4) DO_CHUNK(v5, 5) DO_CHUNK(v6, 6) DO_CHUNK(v7, 7)
#undef DO_CHUNK

        __syncwarp();   // scatter -> scan

        // per-group (max, sum) over exp values; lane owns groups lane, lane+32
        float mx0 = 0.f, sm0 = 0.f, mx1 = 0.f, sm1 = 0.f;
        for (int q = a0 >> 2; q < (b0 >> 2); q++) {
            float4 c = my4[q];
            sm0 += (c.x + c.y) + (c.z + c.w);
            mx0 = fmaxf(mx0, fmaxf(fmaxf(c.x, c.y), fmaxf(c.z, c.w)));
        }
        for (int q = a1 >> 2; q < (b1 >> 2); q++) {
            float4 c = my4[q];
            sm1 += (c.x + c.y) + (c.z + c.w);
            mx1 = fmaxf(mx1, fmaxf(fmaxf(c.x, c.y), fmaxf(c.z, c.w)));
        }
        __syncwarp();   // scan done before next row's scatter

        const int label = __ldg(&labels[row]);
        float candS = (label < 32) ? sm0 : sm1;       // group exp-sum
        float candM = (label < 32) ? mx0 : mx1;       // exp(group max)
        float ls = __shfl_sync(~0u, candS, label & 31);
        float Gl = __shfl_sync(~0u, candM, label & 31);

        float tot = sm0 + sm1;        // full softmax denominator (partial)
        float S   = mx0 + mx1;        // sum of exp(coarse_max) (partial)
#pragma unroll
        for (int o = 16; o; o >>= 1) {
            tot += __shfl_xor_sync(~0u, tot, o);
            S   += __shfl_xor_sync(~0u, S, o);
        }

        if (lane == 0) {
            float ce  = __logf(S) - __logf(Gl);       // lse(cmax) - cmax[label]
            float nll = __logf(tot) - __logf(ls);     // log total - log group sum
            atomicAdd(&g_acc[row & 63], (double)(0.5f * (ce + nll)));
        }
    }

    // ================= Fused finalize (last block) =================
    __syncthreads();
    if (t == 0) {
        __threadfence();
        if (atomicAdd(&g_done, 1) == NBLOCKS - 1) {
            __threadfence();
            double s = 0.0;
#pragma unroll
            for (int i = 0; i < 64; i++) s += g_acc[i];
            out[0] = (float)(s / (double)NROWS);
#pragma unroll
            for (int i = 0; i < 64; i++) g_acc[i] = 0.0;  // reset for replay
            g_done = 0;
            __threadfence();
            *(volatile int*)&g_flag = 0;
        }
    }
}

extern "C" void kernel_launch(void* const* d_in, const int* in_sizes, int n_in,
                              void* d_out, int out_size) {
    const float* logits = (const float*)d_in[0];  // [32, 2048, 1024] f32
    const int*   labels = (const int*)d_in[1];    // [32, 2048] i32
    const float* mask   = (const float*)d_in[2];  // [1024, 64] f32

    mix_kernel<<<NBLOCKS, NTHREADS>>>(logits, labels, mask, (float*)d_out);
}